// round 10
// baseline (speedup 1.0000x reference)
#include <cuda_runtime.h>
#include <cuda_bf16.h>
#include <math_constants.h>

#define B        256
#define N_IN     4096
#define N_MID    4096
#define N_OUT    1024
#define AM_ROWS  (3 * N_IN)     // 12288 virtual rows
#define AM_GRID  1184           // 148 SMs * 8 resident blocks

// Scratch (device globals — no allocation allowed)
__device__ __align__(16) int g_dest1[N_IN];
__device__ __align__(16) int g_dest2[N_MID];
__device__ __align__(16) int g_dest3[N_MID];   // W3 has 4096 rows

// ---------------------------------------------------------------------------
// Persistent grid-stride argmax over all three weight matrices.
// Virtual rows [0,4096)->W1, [4096,8192)->W2, [8192,12288)->W3.
// Per row: front-batched __ldcs float4 loads, fmax tree -> block max,
// index recovery by min over positions equal to the max (ties -> smallest
// index, matching jnp.argmax).
// ---------------------------------------------------------------------------
__global__ void __launch_bounds__(256) argmax_all_kernel(
    const float* __restrict__ W1, const float* __restrict__ W2,
    const float* __restrict__ W3)
{
    const int tid  = threadIdx.x;
    const int lane = tid & 31;
    const int wid  = tid >> 5;

    __shared__ float s_w[8];
    __shared__ int   s_i[8];

    for (int bid = blockIdx.x; bid < AM_ROWS; bid += AM_GRID) {
        const float* W;
        int* dest;
        int row;
        bool wide;
        if (bid < N_IN) {
            W = W1; dest = g_dest1; row = bid;          wide = true;
        } else if (bid < 2 * N_IN) {
            W = W2; dest = g_dest2; row = bid - N_IN;   wide = true;
        } else {
            W = W3; dest = g_dest3; row = bid - 2*N_IN; wide = false;
        }

        float4 a, b, c, d;
        float m;
        if (wide) {
            const float4* __restrict__ r4 =
                reinterpret_cast<const float4*>(W + (size_t)row * N_MID);
            a = __ldcs(r4 + tid);
            b = __ldcs(r4 + tid + 256);
            c = __ldcs(r4 + tid + 512);
            d = __ldcs(r4 + tid + 768);
            float m0 = fmaxf(fmaxf(a.x, a.y), fmaxf(a.z, a.w));
            float m1 = fmaxf(fmaxf(b.x, b.y), fmaxf(b.z, b.w));
            float m2 = fmaxf(fmaxf(c.x, c.y), fmaxf(c.z, c.w));
            float m3 = fmaxf(fmaxf(d.x, d.y), fmaxf(d.z, d.w));
            m = fmaxf(fmaxf(m0, m1), fmaxf(m2, m3));
        } else {
            const float4* __restrict__ r4 =
                reinterpret_cast<const float4*>(W + (size_t)row * N_OUT);
            a = __ldcs(r4 + tid);
            m = fmaxf(fmaxf(a.x, a.y), fmaxf(a.z, a.w));
        }

        // Warp max
        #pragma unroll
        for (int off = 16; off > 0; off >>= 1)
            m = fmaxf(m, __shfl_xor_sync(0xFFFFFFFFu, m, off));

        if (lane == 0) s_w[wid] = m;
        __syncthreads();
        float bm = s_w[0];
        #pragma unroll
        for (int w = 1; w < 8; w++) bm = fmaxf(bm, s_w[w]);

        // Index recovery: smallest global index whose value equals bm.
        int cand = 0x7FFFFFFF;
        if (wide) {
            int g0 = tid*4, g1 = (tid+256)*4, g2 = (tid+512)*4, g3 = (tid+768)*4;
            if (a.x == bm) cand = min(cand, g0    );
            if (a.y == bm) cand = min(cand, g0 + 1);
            if (a.z == bm) cand = min(cand, g0 + 2);
            if (a.w == bm) cand = min(cand, g0 + 3);
            if (b.x == bm) cand = min(cand, g1    );
            if (b.y == bm) cand = min(cand, g1 + 1);
            if (b.z == bm) cand = min(cand, g1 + 2);
            if (b.w == bm) cand = min(cand, g1 + 3);
            if (c.x == bm) cand = min(cand, g2    );
            if (c.y == bm) cand = min(cand, g2 + 1);
            if (c.z == bm) cand = min(cand, g2 + 2);
            if (c.w == bm) cand = min(cand, g2 + 3);
            if (d.x == bm) cand = min(cand, g3    );
            if (d.y == bm) cand = min(cand, g3 + 1);
            if (d.z == bm) cand = min(cand, g3 + 2);
            if (d.w == bm) cand = min(cand, g3 + 3);
        } else {
            int g0 = tid * 4;
            if (a.x == bm) cand = min(cand, g0    );
            if (a.y == bm) cand = min(cand, g0 + 1);
            if (a.z == bm) cand = min(cand, g0 + 2);
            if (a.w == bm) cand = min(cand, g0 + 3);
        }

        #pragma unroll
        for (int off = 16; off > 0; off >>= 1)
            cand = min(cand, __shfl_xor_sync(0xFFFFFFFFu, cand, off));
        if (lane == 0) s_i[wid] = cand;
        __syncthreads();
        if (tid == 0) {
            int i = s_i[0];
            #pragma unroll
            for (int w = 1; w < 8; w++) i = min(i, s_i[w]);
            dest[row] = i;
        }
    }
}

// ---------------------------------------------------------------------------
// Fused compose + scatter. One block (1024 threads) per batch.
// dest2/dest3 (random-access) are staged in smem; dest1 and x are coalesced
// global reads. Each thread: one int4 of x, one int4 of dest1, two dependent
// LDS per element, 4 smem atomics. 36KB smem.
// ---------------------------------------------------------------------------
__global__ void __launch_bounds__(1024) scatter_kernel(
    const int* __restrict__ x, float* __restrict__ out)
{
    __shared__ int sd2[N_MID];   // 16KB
    __shared__ int sd3[N_MID];   // 16KB
    __shared__ int acc[N_OUT];   // 4KB

    const int b   = blockIdx.x;
    const int tid = threadIdx.x;

    // Stage routing tables (coalesced int4, L2-hot)
    reinterpret_cast<int4*>(sd2)[tid] =
        reinterpret_cast<const int4*>(g_dest2)[tid];
    reinterpret_cast<int4*>(sd3)[tid] =
        reinterpret_cast<const int4*>(g_dest3)[tid];
    if (tid < N_OUT) acc[tid] = 0;
    __syncthreads();

    const int4* __restrict__ xb4 =
        reinterpret_cast<const int4*>(x + (size_t)b * N_IN);
    int4 v  = __ldcs(xb4 + tid);                         // DRAM stream
    int4 d1 = reinterpret_cast<const int4*>(g_dest1)[tid]; // L2-hot

    atomicAdd(&acc[sd3[sd2[d1.x]]], v.x);
    atomicAdd(&acc[sd3[sd2[d1.y]]], v.y);
    atomicAdd(&acc[sd3[sd2[d1.z]]], v.z);
    atomicAdd(&acc[sd3[sd2[d1.w]]], v.w);
    __syncthreads();

    if (tid < N_OUT)
        out[(size_t)b * N_OUT + tid] = (float)acc[tid];
}

// ---------------------------------------------------------------------------
extern "C" void kernel_launch(void* const* d_in, const int* in_sizes, int n_in,
                              void* d_out, int out_size)
{
    const int*   x  = (const int*)d_in[0];
    const float* W1 = (const float*)d_in[1];
    const float* W2 = (const float*)d_in[2];
    const float* W3 = (const float*)d_in[3];
    float* out = (float*)d_out;

    argmax_all_kernel<<<AM_GRID, 256>>>(W1, W2, W3);
    scatter_kernel<<<B, 1024>>>(x, out);
}

// round 14
// speedup vs baseline: 1.1979x; 1.1979x over previous
#include <cuda_runtime.h>
#include <cuda_bf16.h>
#include <math_constants.h>

#define B        256
#define N_IN     4096
#define N_MID    4096
#define N_OUT    1024

// Scratch (device globals — no allocation allowed)
__device__ __align__(16) int g_dest1[N_IN];
__device__ __align__(16) int g_dest2[N_MID];
__device__ __align__(16) int g_dest3[N_MID];   // W3 has 4096 rows
__device__ __align__(16) int g_route[N_IN];    // dest3[dest2[dest1[s]]]

// ---------------------------------------------------------------------------
// Fused argmax over all three weight matrices (R8 winner, unchanged).
// Blocks [0,4096)->W1, [4096,8192)->W2, [8192,12288)->W3.
// ---------------------------------------------------------------------------
__global__ void __launch_bounds__(256) argmax_all_kernel(
    const float* __restrict__ W1, const float* __restrict__ W2,
    const float* __restrict__ W3)
{
    const int bid = blockIdx.x;
    const int tid = threadIdx.x;
    const int lane = tid & 31;
    const int wid  = tid >> 5;

    const float* W;
    int* dest;
    int row;
    bool wide;
    if (bid < N_IN) {
        W = W1; dest = g_dest1; row = bid;          wide = true;
    } else if (bid < 2 * N_IN) {
        W = W2; dest = g_dest2; row = bid - N_IN;   wide = true;
    } else {
        W = W3; dest = g_dest3; row = bid - 2*N_IN; wide = false;
    }

    float4 a, b, c, d;
    float m;
    if (wide) {
        const float4* __restrict__ r4 =
            reinterpret_cast<const float4*>(W + (size_t)row * N_MID);
        a = r4[tid];
        b = r4[tid + 256];
        c = r4[tid + 512];
        d = r4[tid + 768];
        float m0 = fmaxf(fmaxf(a.x, a.y), fmaxf(a.z, a.w));
        float m1 = fmaxf(fmaxf(b.x, b.y), fmaxf(b.z, b.w));
        float m2 = fmaxf(fmaxf(c.x, c.y), fmaxf(c.z, c.w));
        float m3 = fmaxf(fmaxf(d.x, d.y), fmaxf(d.z, d.w));
        m = fmaxf(fmaxf(m0, m1), fmaxf(m2, m3));
    } else {
        const float4* __restrict__ r4 =
            reinterpret_cast<const float4*>(W + (size_t)row * N_OUT);
        a = r4[tid];
        m = fmaxf(fmaxf(a.x, a.y), fmaxf(a.z, a.w));
    }

    #pragma unroll
    for (int off = 16; off > 0; off >>= 1)
        m = fmaxf(m, __shfl_xor_sync(0xFFFFFFFFu, m, off));

    __shared__ float s_w[8];
    __shared__ int   s_i[8];
    if (lane == 0) s_w[wid] = m;
    __syncthreads();
    float bm = s_w[0];
    #pragma unroll
    for (int w = 1; w < 8; w++) bm = fmaxf(bm, s_w[w]);

    int cand = 0x7FFFFFFF;
    if (wide) {
        int g0 = tid*4, g1 = (tid+256)*4, g2 = (tid+512)*4, g3 = (tid+768)*4;
        if (a.x == bm) cand = min(cand, g0    );
        if (a.y == bm) cand = min(cand, g0 + 1);
        if (a.z == bm) cand = min(cand, g0 + 2);
        if (a.w == bm) cand = min(cand, g0 + 3);
        if (b.x == bm) cand = min(cand, g1    );
        if (b.y == bm) cand = min(cand, g1 + 1);
        if (b.z == bm) cand = min(cand, g1 + 2);
        if (b.w == bm) cand = min(cand, g1 + 3);
        if (c.x == bm) cand = min(cand, g2    );
        if (c.y == bm) cand = min(cand, g2 + 1);
        if (c.z == bm) cand = min(cand, g2 + 2);
        if (c.w == bm) cand = min(cand, g2 + 3);
        if (d.x == bm) cand = min(cand, g3    );
        if (d.y == bm) cand = min(cand, g3 + 1);
        if (d.z == bm) cand = min(cand, g3 + 2);
        if (d.w == bm) cand = min(cand, g3 + 3);
    } else {
        int g0 = tid * 4;
        if (a.x == bm) cand = min(cand, g0    );
        if (a.y == bm) cand = min(cand, g0 + 1);
        if (a.z == bm) cand = min(cand, g0 + 2);
        if (a.w == bm) cand = min(cand, g0 + 3);
    }

    #pragma unroll
    for (int off = 16; off > 0; off >>= 1)
        cand = min(cand, __shfl_xor_sync(0xFFFFFFFFu, cand, off));
    if (lane == 0) s_i[wid] = cand;
    __syncthreads();
    if (tid == 0) {
        int i = s_i[0];
        #pragma unroll
        for (int w = 1; w < 8; w++) i = min(i, s_i[w]);
        dest[row] = i;
    }
}

// ---------------------------------------------------------------------------
// Compose route once (PDL secondary of argmax): waits for the argmax grid,
// then chases the L2-hot tables. route[s] = dest3[dest2[dest1[s]]].
// ---------------------------------------------------------------------------
__global__ void __launch_bounds__(256) compose_kernel()
{
#if __CUDA_ARCH__ >= 900
    cudaGridDependencySynchronize();
#endif
    int s = blockIdx.x * 256 + threadIdx.x;
    g_route[s] = g_dest3[g_dest2[g_dest1[s]]];
}

// ---------------------------------------------------------------------------
// Scatter (PDL secondary of compose): the preamble — DRAM x-load and acc
// zeroing — runs while argmax/compose are still draining; only the route
// read waits on the dependency.
// ---------------------------------------------------------------------------
__global__ void __launch_bounds__(1024) scatter_kernel(
    const int* __restrict__ x, float* __restrict__ out)
{
    __shared__ int acc[N_OUT];
    const int b   = blockIdx.x;
    const int tid = threadIdx.x;

    // Preamble: independent of route — overlaps with upstream kernels.
    const int4* __restrict__ xb4 =
        reinterpret_cast<const int4*>(x + (size_t)b * N_IN);
    int4 v = xb4[tid];               // DRAM stream, coalesced
    if (tid < N_OUT) acc[tid] = 0;
    __syncthreads();

#if __CUDA_ARCH__ >= 900
    cudaGridDependencySynchronize();
#endif
    int4 r = reinterpret_cast<const int4*>(g_route)[tid];  // L2-hot
    atomicAdd(&acc[r.x], v.x);
    atomicAdd(&acc[r.y], v.y);
    atomicAdd(&acc[r.z], v.z);
    atomicAdd(&acc[r.w], v.w);
    __syncthreads();

    if (tid < N_OUT)
        out[(size_t)b * N_OUT + tid] = (float)acc[tid];
}

// ---------------------------------------------------------------------------
static void launch_pdl(const void* fn, dim3 grid, dim3 block,
                       void** args)
{
    cudaLaunchConfig_t cfg = {};
    cfg.gridDim  = grid;
    cfg.blockDim = block;
    cfg.dynamicSmemBytes = 0;
    cfg.stream = 0;                      // legacy default stream (captured)
    cudaLaunchAttribute attr[1];
    attr[0].id = cudaLaunchAttributeProgrammaticStreamSerialization;
    attr[0].val.programmaticStreamSerializationAllowed = 1;
    cfg.attrs = attr;
    cfg.numAttrs = 1;
    cudaLaunchKernelExC(&cfg, fn, args);
}

extern "C" void kernel_launch(void* const* d_in, const int* in_sizes, int n_in,
                              void* d_out, int out_size)
{
    const int*   x  = (const int*)d_in[0];
    const float* W1 = (const float*)d_in[1];
    const float* W2 = (const float*)d_in[2];
    const float* W3 = (const float*)d_in[3];
    float* out = (float*)d_out;

    argmax_all_kernel<<<3 * N_IN, 256>>>(W1, W2, W3);

    void* compose_args[] = {};
    launch_pdl((const void*)compose_kernel, dim3(N_IN / 256), dim3(256),
               compose_args);

    void* scatter_args[] = {(void*)&x, (void*)&out};
    launch_pdl((const void*)scatter_kernel, dim3(B), dim3(1024),
               scatter_args);
}